// round 3
// baseline (speedup 1.0000x reference)
#include <cuda_runtime.h>
#include <math.h>

#define BATCH   1024
#define SEQ     200
#define HID     128
#define VOCAB   100000
#define PAD_ID      99998
#define INTEREST_ID 99999
#define NTHR    256

__global__ __launch_bounds__(NTHR) void repeat_decoder_kernel(
    const float* __restrict__ hs,   // (B, S, H) fp32
    const int*   __restrict__ ids,  // (B, S) int32 (jax x64-disabled downcast)
    const float* __restrict__ w,    // (H,)
    const float* __restrict__ bp,   // (1,)
    float* __restrict__ out)        // (B, VOCAB) fp32
{
    const int b    = blockIdx.x;
    const int tid  = threadIdx.x;
    const int lane = tid & 31;
    const int warp = tid >> 5;

    __shared__ float s_scores[SEQ];
    __shared__ float red[8];

    // ---- Phase 0: zero this batch's output row (400 KB, float4 stores) ----
    float4* row4 = reinterpret_cast<float4*>(out + (size_t)b * VOCAB);
    const float4 z = make_float4(0.f, 0.f, 0.f, 0.f);
    #pragma unroll 4
    for (int i = tid; i < VOCAB / 4; i += NTHR) row4[i] = z;

    // ---- Phase 1: scores[s] = dot(tanh(h[b,s]+h[b,0]), w) + bias ----
    // lane l owns H-elements [4l, 4l+4)
    const float4* hb  = reinterpret_cast<const float4*>(hs + (size_t)b * SEQ * HID);
    const float4  key = hb[lane];                               // hidden[b,0,:]
    const float4  wp  = reinterpret_cast<const float4*>(w)[lane];
    const float   bias = bp[0];

    for (int s = warp; s < SEQ; s += 8) {
        float4 hv = hb[s * (HID / 4) + lane];
        float p = tanhf(hv.x + key.x) * wp.x
                + tanhf(hv.y + key.y) * wp.y
                + tanhf(hv.z + key.z) * wp.z
                + tanhf(hv.w + key.w) * wp.w;
        #pragma unroll
        for (int o = 16; o; o >>= 1) p += __shfl_xor_sync(0xffffffffu, p, o);
        if (lane == 0) s_scores[s] = p + bias;
    }
    __syncthreads();

    // ---- Phase 2: masked softmax over S, then scatter-add ----
    int   my_id    = 0;
    bool  my_valid = false;
    float my_sc    = -INFINITY;
    if (tid < SEQ) {
        my_id    = ids[(size_t)b * SEQ + tid];
        my_valid = (my_id != PAD_ID) && (my_id != INTEREST_ID);
        my_sc    = my_valid ? s_scores[tid] : -INFINITY;
    }

    // block-reduce max
    float m = my_sc;
    #pragma unroll
    for (int o = 16; o; o >>= 1) m = fmaxf(m, __shfl_xor_sync(0xffffffffu, m, o));
    if (lane == 0) red[warp] = m;
    __syncthreads();
    if (warp == 0) {
        float mm = red[lane & 7];
        #pragma unroll
        for (int o = 4; o; o >>= 1) mm = fmaxf(mm, __shfl_xor_sync(0xffffffffu, mm, o));
        if (lane == 0) red[0] = mm;
    }
    __syncthreads();
    m = red[0];

    // exp and block-reduce sum
    float e = (tid < SEQ && my_valid) ? expf(my_sc - m) : 0.f;
    float ssum = e;
    #pragma unroll
    for (int o = 16; o; o >>= 1) ssum += __shfl_xor_sync(0xffffffffu, ssum, o);
    __syncthreads();               // red[] reuse
    if (lane == 0) red[warp] = ssum;
    __syncthreads();
    if (warp == 0) {
        float tt = red[lane & 7];
        #pragma unroll
        for (int o = 4; o; o >>= 1) tt += __shfl_xor_sync(0xffffffffu, tt, o);
        if (lane == 0) red[0] = tt;
    }
    __syncthreads();
    const float inv_sum = 1.0f / red[0];

    // scatter (row is private to this block; zero-fill done before the syncs above)
    if (tid < SEQ && my_valid) {
        atomicAdd(out + (size_t)b * VOCAB + my_id, e * inv_sum);
    }
}

extern "C" void kernel_launch(void* const* d_in, const int* in_sizes, int n_in,
                              void* d_out, int out_size) {
    const float* hs  = (const float*)d_in[0];
    const int*   ids = (const int*)d_in[1];
    const float* w   = (const float*)d_in[2];
    const float* bp  = (const float*)d_in[3];
    float*       out = (float*)d_out;
    repeat_decoder_kernel<<<BATCH, NTHR>>>(hs, ids, w, bp, out);
}

// round 4
// speedup vs baseline: 1.0211x; 1.0211x over previous
#include <cuda_runtime.h>
#include <math.h>

#define BATCH   1024
#define SEQ     200
#define HID     128
#define VOCAB   100000
#define PAD_ID      99998
#define INTEREST_ID 99999
#define NTHR    256
#define ROW4    (VOCAB / 4)      // 25000 float4 per output row

__global__ __launch_bounds__(NTHR) void repeat_decoder_kernel(
    const float* __restrict__ hs,   // (B, S, H) fp32
    const int*   __restrict__ ids,  // (B, S) int32
    const float* __restrict__ w,    // (H,)
    const float* __restrict__ bp,   // (1,)
    float* __restrict__ out)        // (B, VOCAB) fp32
{
    const int b    = blockIdx.x;
    const int tid  = threadIdx.x;
    const int lane = tid & 31;
    const int warp = tid >> 5;

    __shared__ float s_scores[SEQ];
    __shared__ float red[8];

    float4* row4 = reinterpret_cast<float4*>(out + (size_t)b * VOCAB);
    const float4 z = make_float4(0.f, 0.f, 0.f, 0.f);

    // lane l owns H-elements [4l, 4l+4)
    const float4* hb  = reinterpret_cast<const float4*>(hs + (size_t)b * SEQ * HID);
    const float4  key = hb[lane];                               // hidden[b,0,:]
    const float4  wp  = reinterpret_cast<const float4*>(w)[lane];
    const float   bias = bp[0];

    // ---- Fused: score computation (reads) interleaved with zero-fill (writes) ----
    // 25 score iterations per warp; 4 zero float4-stores per thread per iteration
    // covers 25*4*256 = 25600 >= 25000 slots.
    #pragma unroll 1
    for (int j = 0; j < 25; ++j) {
        const int s = warp + 8 * j;
        float4 hv = hb[s * (HID / 4) + lane];

        // issue the zero stores while the load is in flight
        #pragma unroll
        for (int k = 0; k < 4; ++k) {
            int i = tid + NTHR * (4 * j + k);
            if (i < ROW4) row4[i] = z;
        }

        float p = tanhf(hv.x + key.x) * wp.x
                + tanhf(hv.y + key.y) * wp.y
                + tanhf(hv.z + key.z) * wp.z
                + tanhf(hv.w + key.w) * wp.w;
        #pragma unroll
        for (int o = 16; o; o >>= 1) p += __shfl_xor_sync(0xffffffffu, p, o);
        if (lane == 0) s_scores[s] = p + bias;
    }
    __syncthreads();

    // ---- Masked softmax over S, then scatter-add ----
    int   my_id    = 0;
    bool  my_valid = false;
    float my_sc    = -INFINITY;
    if (tid < SEQ) {
        my_id    = ids[(size_t)b * SEQ + tid];
        my_valid = (my_id != PAD_ID) && (my_id != INTEREST_ID);
        my_sc    = my_valid ? s_scores[tid] : -INFINITY;
    }

    // block-reduce max
    float m = my_sc;
    #pragma unroll
    for (int o = 16; o; o >>= 1) m = fmaxf(m, __shfl_xor_sync(0xffffffffu, m, o));
    if (lane == 0) red[warp] = m;
    __syncthreads();
    if (warp == 0) {
        float mm = red[lane & 7];
        #pragma unroll
        for (int o = 4; o; o >>= 1) mm = fmaxf(mm, __shfl_xor_sync(0xffffffffu, mm, o));
        if (lane == 0) red[0] = mm;
    }
    __syncthreads();
    m = red[0];

    // exp and block-reduce sum
    float e = (tid < SEQ && my_valid) ? expf(my_sc - m) : 0.f;
    float ssum = e;
    #pragma unroll
    for (int o = 16; o; o >>= 1) ssum += __shfl_xor_sync(0xffffffffu, ssum, o);
    __syncthreads();               // red[] reuse
    if (lane == 0) red[warp] = ssum;
    __syncthreads();
    if (warp == 0) {
        float tt = red[lane & 7];
        #pragma unroll
        for (int o = 4; o; o >>= 1) tt += __shfl_xor_sync(0xffffffffu, tt, o);
        if (lane == 0) red[0] = tt;
    }
    __syncthreads();
    const float inv_sum = 1.0f / red[0];

    // scatter (row private to this block; zero-fill ordered by the syncthreads above)
    if (tid < SEQ && my_valid) {
        atomicAdd(out + (size_t)b * VOCAB + my_id, e * inv_sum);
    }
}

extern "C" void kernel_launch(void* const* d_in, const int* in_sizes, int n_in,
                              void* d_out, int out_size) {
    const float* hs  = (const float*)d_in[0];
    const int*   ids = (const int*)d_in[1];
    const float* w   = (const float*)d_in[2];
    const float* bp  = (const float*)d_in[3];
    float*       out = (float*)d_out;
    repeat_decoder_kernel<<<BATCH, NTHR>>>(hs, ids, w, bp, out);
}